// round 5
// baseline (speedup 1.0000x reference)
#include <cuda_runtime.h>
#include <math.h>

// Fixed shapes: B=32, S=128, V=8, T=66 -> 256 independent sequences.
// ONE WARP per sequence, 2 warps (2 seqs) per 64-thread block, 128 blocks.
// No block barriers anywhere in the scan; warp-private smem only.
#define TT   66
#define SS   128
#define NSEQ 256
#define NBLK 128
#define USTRIDE 72   // u buffer stride (floats), 16B-aligned ping-pong

typedef unsigned long long ull;

__device__ float        g_partial[NSEQ];
__device__ unsigned int g_count = 0;

static __device__ __forceinline__ ull pk2(float lo, float hi) {
    ull r; asm("mov.b64 %0, {%1,%2};" : "=l"(r) : "f"(lo), "f"(hi)); return r;
}
static __device__ __forceinline__ void fma2(ull& d, ull a, ull b) {
    asm("fma.rn.f32x2 %0, %1, %2, %0;" : "+l"(d) : "l"(a), "l"(b));
}
static __device__ __forceinline__ void add2(ull& d, ull a, ull b) {
    asm("add.rn.f32x2 %0, %1, %2;" : "=l"(d) : "l"(a), "l"(b));
}
static __device__ __forceinline__ float2 upk2(ull v) {
    float lo, hi; asm("mov.b64 {%0,%1}, %2;" : "=f"(lo), "=f"(hi) : "l"(v));
    return make_float2(lo, hi);
}

// smem: expEmis[2][SS*TT] + ubuf[2 warps][2][USTRIDE] + sred[2]
#define SMEM_FLOATS (2*SS*TT + 2*2*USTRIDE + 4)
#define SMEM_BYTES  (SMEM_FLOATS*4)

__global__ void __launch_bounds__(64) crf_kernel(
    const float* __restrict__ score,       // [B,S,S,T]
    const float* __restrict__ trans,       // [T,T]
    const float* __restrict__ startT,      // [T]
    const float* __restrict__ endT,        // [T]
    const int*   __restrict__ v_label,     // [B*V]
    const int*   __restrict__ role_label,  // [B*V][S]
    float*       __restrict__ out)
{
    extern __shared__ __align__(16) float sm[];
    float* emis = sm;                       // [2][SS*TT] exp(emissions)
    float* ubuf = sm + 2*SS*TT;             // [2][2][USTRIDE]
    float* sred = ubuf + 4*USTRIDE;         // [2]
    int*   sflag = (int*)(sred + 2);

    const int tid  = threadIdx.x;
    const int lane = tid & 31;
    const int w    = tid >> 5;
    const int seq  = blockIdx.x*2 + w;
    const int b    = seq >> 3;              // V = 8
    const int vr   = __ldg(&v_label[seq]);
    const float* erow = score + ((size_t)(b*SS + vr))*SS*TT;

    float* esh = emis + w*SS*TT;
    float* ub  = ubuf + w*2*USTRIDE;        // ping-pong: ub, ub+USTRIDE

    // ---- gold path first (long-latency dependent gathers overlap the rest) ----
    float gold = 0.f;
    #pragma unroll
    for (int p = 0; p < 4; p++) {
        int s  = lane + 32*p;
        int tg = __ldg(&role_label[seq*SS + s]);
        float gg = __ldg(&erow[s*TT + tg]);
        if (s < SS-1) gg += __ldg(&trans[tg*TT + __ldg(&role_label[seq*SS + s + 1])]);
        else          gg += __ldg(&endT[tg]);
        if (s == 0)   gg += __ldg(&startT[tg]);
        gold += gg;
    }
    #pragma unroll
    for (int o = 16; o; o >>= 1) gold += __shfl_xor_sync(~0u, gold, o);

    // ---- prologue: copy emissions to smem fused with exp ----
    {
        const float4* src = (const float4*)erow;
        float4*       dst = (float4*)esh;
        #pragma unroll 4
        for (int k = lane; k < (SS*TT)/4; k += 32) {
            float4 v = __ldg(&src[k]);
            v.x = __expf(v.x); v.y = __expf(v.y);
            v.z = __expf(v.z); v.w = __expf(v.w);
            dst[k] = v;
        }
    }
    // zero u pads (floats 66..71 of both buffers)
    if (lane < 6) { ub[66 + lane] = 0.f; ub[USTRIDE + 66 + lane] = 0.f; }

    // ---- E registers: dual-interleaved column pair (c0, c1) = (2l, 2l+1) ----
    // eA[m] = (E[2m][c0], E[2m+1][c1]);  eB[m] = (E[2m][c1], E[2m+1][c0])
    ull eA[33], eB[33];
    #pragma unroll
    for (int m = 0; m < 33; m++) {
        float2 f0 = __ldg((const float2*)(trans + (2*m  )*TT) + lane);
        float2 f1 = __ldg((const float2*)(trans + (2*m+1)*TT) + lane);
        float a = __expf(f0.x), bb = __expf(f0.y);
        float cee = __expf(f1.x), d = __expf(f1.y);
        eA[m] = pk2(a, d);
        eB[m] = pk2(bb, cee);
    }
    // extra columns 64,65: 8-way redundant, group g handles u-pairs 4g..4g+3 (+pair32 on g0)
    const int g = lane & 7;
    ull xA[5], xB[5];
    #pragma unroll
    for (int q = 0; q < 4; q++) {
        int rr = 2*(4*g + q);
        float2 h0 = __ldg((const float2*)(trans + rr*TT + 64));
        float2 h1 = __ldg((const float2*)(trans + (rr+1)*TT + 64));
        xA[q] = pk2(__expf(h0.x), __expf(h1.y));
        xB[q] = pk2(__expf(h0.y), __expf(h1.x));
    }
    if (g == 0) {
        float2 h0 = __ldg((const float2*)(trans + 64*TT + 64));
        float2 h1 = __ldg((const float2*)(trans + 65*TT + 64));
        xA[4] = pk2(__expf(h0.x), __expf(h1.y));
        xB[4] = pk2(__expf(h0.y), __expf(h1.x));
    } else { xA[4] = 0ULL; xB[4] = 0ULL; }

    float2 stc  = __ldg((const float2*)startT + lane);
    float2 stx  = __ldg((const float2*)(startT + 64));
    float2 endc = __ldg((const float2*)endT + lane);
    float2 endx = __ldg((const float2*)(endT + 64));
    float eE0 = __expf(endc.x), eE1 = __expf(endc.y);
    float eEx = __expf(endx.x), eEy = __expf(endx.y);

    __syncwarp();    // esh visible to whole warp

    // ---- u0 = exp(start) * expEmis[0] ----
    float r0   = __expf(stc.x) * esh[2*lane];
    float r1   = __expf(stc.y) * esh[2*lane + 1];
    float x64v = __expf(stx.x) * esh[64];
    float x65v = __expf(stx.y) * esh[65];
    ((float2*)ub)[lane] = make_float2(r0, r1);
    if (lane == 0) *(float2*)(ub + 64) = make_float2(x64v, x65v);

    float m0 = fmaxf(fmaxf(r0, r1), fmaxf(x64v, x65v));
    #pragma unroll
    for (int o = 16; o; o >>= 1) m0 = fmaxf(m0, __shfl_xor_sync(~0u, m0, o));
    float sc = __fdividef(1.0f, m0);
    float L  = __logf(m0);
    __syncwarp();

    // ---- one scan step (pure LDS/FMA2/shfl; no LDG, no MUFU, no barrier) ----
    auto STEP = [&](int t, const float* uc, float* un, float scale) {
        float2 em  = *((const float2*)(esh + t*TT) + lane);
        float2 emx = *(const float2*)(esh + t*TT + 64);
        ull dA0 = 0, dA1 = 0, dB0 = 0, dB1 = 0;
        const ulonglong2* up = (const ulonglong2*)uc;
        #pragma unroll
        for (int i = 0; i < 16; i++) {
            ulonglong2 va = up[i];
            fma2(dA0, va.x, eA[2*i]);   fma2(dB0, va.x, eB[2*i]);
            fma2(dA1, va.y, eA[2*i+1]); fma2(dB1, va.y, eB[2*i+1]);
        }
        ull last = *(const ull*)(uc + 64);           // pair 32 = (u64,u65)
        fma2(dA0, last, eA[32]); fma2(dB0, last, eB[32]);
        // extra columns 64/65: group-redundant partials
        const ulonglong2* ux = (const ulonglong2*)(uc + 8*g);
        ulonglong2 va0 = ux[0], va1 = ux[1];
        ull XA = 0, XB = 0;
        fma2(XA, va0.x, xA[0]); fma2(XB, va0.x, xB[0]);
        fma2(XA, va0.y, xA[1]); fma2(XB, va0.y, xB[1]);
        fma2(XA, va1.x, xA[2]); fma2(XB, va1.x, xB[2]);
        fma2(XA, va1.y, xA[3]); fma2(XB, va1.y, xB[3]);
        fma2(XA, last,  xA[4]); fma2(XB, last,  xB[4]);
        float2 fa = upk2(XA), fb = upk2(XB);
        float px = fa.x + fb.y;
        float py = fa.y + fb.x;
        px += __shfl_xor_sync(~0u, px, 1);  py += __shfl_xor_sync(~0u, py, 1);
        px += __shfl_xor_sync(~0u, px, 2);  py += __shfl_xor_sync(~0u, py, 2);
        px += __shfl_xor_sync(~0u, px, 4);  py += __shfl_xor_sync(~0u, py, 4);
        add2(dA0, dA0, dA1); add2(dB0, dB0, dB1);
        float2 A = upk2(dA0), Bv = upk2(dB0);
        r0   = (A.x + Bv.y) * (scale * em.x);
        r1   = (A.y + Bv.x) * (scale * em.y);
        x64v = px * (scale * emx.x);
        x65v = py * (scale * emx.y);
        ((float2*)un)[lane] = make_float2(r0, r1);
        if (lane == 0) *(float2*)(un + 64) = make_float2(x64v, x65v);
        __syncwarp();
    };

    // ---- main scan: 15 groups of 8 + 7-step tail; renorm at group boundaries ----
    float* uc = ub;
    float* un = ub + USTRIDE;
    int t = 1;
    for (int grp = 0; grp < 16; grp++) {
        const int nsteps = (grp == 15) ? 7 : 8;
        #pragma unroll 8
        for (int q = 0; q < nsteps; q++) {
            STEP(t, uc, un, (q == 0) ? sc : 1.0f);
            float* tmp = uc; uc = un; un = tmp;
            t++;
        }
        if (grp < 15) {
            float mm = fmaxf(fmaxf(r0, r1), fmaxf(x64v, x65v));
            #pragma unroll
            for (int o = 16; o; o >>= 1) mm = fmaxf(mm, __shfl_xor_sync(~0u, mm, o));
            sc = __fdividef(1.0f, mm);
            L += __logf(mm);
        }
    }

    // ---- epilogue: logZ = log(sum_j u_j * exp(end_j)) + L ----
    float ws = r0 * eE0 + r1 * eE1;
    #pragma unroll
    for (int o = 16; o; o >>= 1) ws += __shfl_xor_sync(~0u, ws, o);
    if (lane == 0) {
        ws += x64v * eEx + x65v * eEy;      // all lanes hold x64v/x65v; add once
        __stcg(&g_partial[seq], __logf(ws) + L - gold);
    }
    __threadfence();
    __syncthreads();                        // both warps of block done

    if (tid == 0) {
        unsigned cc = atomicAdd(&g_count, 1u);
        *sflag = (cc == NBLK - 1) ? 1 : 0;
    }
    __syncthreads();

    // ---- fused final reduction in the last block ----
    if (*sflag) {
        float v = 0.f;
        #pragma unroll
        for (int p = 0; p < 4; p++) v += __ldcg(&g_partial[tid + 64*p]);
        #pragma unroll
        for (int o = 16; o; o >>= 1) v += __shfl_xor_sync(~0u, v, o);
        if (lane == 0) sred[w] = v;
        __syncthreads();
        if (tid == 0) {
            out[0] = (sred[0] + sred[1]) * (1.0f / (float)NSEQ);
            g_count = 0;                    // reset for next graph replay
        }
    }
}

extern "C" void kernel_launch(void* const* d_in, const int* in_sizes, int n_in,
                              void* d_out, int out_size) {
    const float* score      = (const float*)d_in[0];
    const float* trans      = (const float*)d_in[1];
    const float* startT     = (const float*)d_in[2];
    const float* endT       = (const float*)d_in[3];
    const int*   v_label    = (const int*)d_in[4];
    const int*   role_label = (const int*)d_in[5];
    float* out = (float*)d_out;

    cudaFuncSetAttribute(crf_kernel,
                         cudaFuncAttributeMaxDynamicSharedMemorySize, SMEM_BYTES);

    crf_kernel<<<NBLK, 64, SMEM_BYTES>>>(
        score, trans, startT, endT, v_label, role_label, out);
}

// round 6
// speedup vs baseline: 1.0063x; 1.0063x over previous
#include <cuda_runtime.h>
#include <math.h>

// Fixed shapes: B=32, S=128, V=8, T=66 -> 256 independent sequences.
// One block per sequence, 136 threads (5 warps). Work slot = (column, row-half):
// thread t<132: col = t>>1, half = t&1. Cols 64,65 live in warp 4 naturally.
#define TT   66
#define SS   128
#define NSEQ 256
#define NTHR 136
#define NW   5
#define USTR 72          // u ping-pong stride (floats)

typedef unsigned long long ull;

__device__ float        g_partial[NSEQ];
__device__ unsigned int g_count = 0;

static __device__ __forceinline__ ull pk2(float lo, float hi) {
    ull r; asm("mov.b64 %0, {%1,%2};" : "=l"(r) : "f"(lo), "f"(hi)); return r;
}
static __device__ __forceinline__ void fma2(ull& d, ull a, ull b) {
    asm("fma.rn.f32x2 %0, %1, %2, %0;" : "+l"(d) : "l"(a), "l"(b));
}
static __device__ __forceinline__ void add2(ull& d, ull a, ull b) {
    asm("add.rn.f32x2 %0, %1, %2;" : "=l"(d) : "l"(a), "l"(b));
}
static __device__ __forceinline__ float2 upk2(ull v) {
    float lo, hi; asm("mov.b64 {%0,%1}, %2;" : "=f"(lo), "=f"(hi) : "l"(v));
    return make_float2(lo, hi);
}

// u buffer layout (per ping-pong slab of USTR floats):
//   floats [0..31]  = u[0..31]        (read by half 0 at byte 0)
//   floats [36..67] = u[32..63]       (read by half 1 at byte 144 -> different banks)
//   floats [68..69] = u[64..65]       (pair 32, read by all)
// writer location for col c: loc = c + (c >= 32 ? 4 : 0)
#define SMEM_FLOATS (SS*TT + 2*USTR + 4*NW + 4)
#define SMEM_BYTES  (SMEM_FLOATS*4)

__global__ void __launch_bounds__(NTHR) crf_kernel(
    const float* __restrict__ score,       // [B,S,S,T]
    const float* __restrict__ trans,       // [T,T]
    const float* __restrict__ startT,      // [T]
    const float* __restrict__ endT,        // [T]
    const int*   __restrict__ v_label,     // [B*V]
    const int*   __restrict__ role_label,  // [B*V][S]
    float*       __restrict__ out)
{
    extern __shared__ __align__(16) float sm[];
    float* esh   = sm;                     // [SS][TT] exp(emissions)
    float* ub    = sm + SS*TT;             // [2][USTR] ping-pong u
    float* wmax  = ub + 2*USTR;            // [NW]
    float* sgold = wmax + NW;              // [NW]
    float* swsum = sgold + NW;             // [NW]
    float* wred  = swsum + NW;             // [NW]
    int*   sflag = (int*)(wred + NW);

    const int tid  = threadIdx.x;
    const int lane = tid & 31;
    const int wid  = tid >> 5;
    const int seq  = blockIdx.x;
    const int b    = seq >> 3;             // V = 8
    const int vr   = __ldg(&v_label[seq]);
    const float* erow = score + ((size_t)(b*SS + vr))*SS*TT;

    const bool act = (tid < 132);
    const int  cc  = act ? (tid >> 1) : 0; // my column
    const int  h   = tid & 1;              // my row half
    const int  loc = cc + ((cc >= 32) ? 4 : 0);

    // ---- gold path: one position per thread (tid < 128) ----
    float gold = 0.f;
    if (tid < 128) {
        int s  = tid;
        int tg = __ldg(&role_label[seq*SS + s]);
        gold = __ldg(&erow[s*TT + tg]);
        if (s < SS-1) gold += __ldg(&trans[tg*TT + __ldg(&role_label[seq*SS + s + 1])]);
        else          gold += __ldg(&endT[tg]);
        if (s == 0)   gold += __ldg(&startT[tg]);
    }
    #pragma unroll
    for (int o = 16; o; o >>= 1) gold += __shfl_xor_sync(~0u, gold, o);
    if (lane == 0) sgold[wid] = gold;

    // ---- prologue: exp(emissions) into smem ----
    {
        const float4* src = (const float4*)erow;
        float4*       dst = (float4*)esh;
        #pragma unroll 4
        for (int k = tid; k < (SS*TT)/4; k += NTHR) {
            float4 v = __ldg(&src[k]);
            v.x = __expf(v.x); v.y = __expf(v.y);
            v.z = __expf(v.z); v.w = __expf(v.w);
            dst[k] = v;
        }
    }

    // ---- exp(trans) rows for my (col, half): 17 packed row-pairs ----
    // h=0: rows 0..31 (pairs 0..15) + rows 64,65 (e[16]); h=1: rows 32..63, e[16]=0
    ull e[17];
    if (act) {
        #pragma unroll
        for (int k = 0; k < 16; k++) {
            int rr = h*32 + 2*k;
            e[k] = pk2(__expf(__ldg(&trans[rr*TT + cc])),
                       __expf(__ldg(&trans[(rr+1)*TT + cc])));
        }
        e[16] = (h == 0) ? pk2(__expf(__ldg(&trans[64*TT + cc])),
                               __expf(__ldg(&trans[65*TT + cc]))) : 0ULL;
    } else {
        #pragma unroll
        for (int k = 0; k < 17; k++) e[k] = 0ULL;
    }
    const float eE = (act && h == 0) ? __expf(__ldg(&endT[cc])) : 0.f;
    const float st = act ? __expf(__ldg(&startT[cc])) : 0.f;

    __syncthreads();   // esh ready

    // ---- u0 = exp(start) * expEmis[0]; initial renorm ----
    float r = act ? (st * esh[cc]) : 0.f;
    if (act && h == 0) ub[loc] = r;
    {
        float mm = r;
        #pragma unroll
        for (int o = 16; o; o >>= 1) mm = fmaxf(mm, __shfl_xor_sync(~0u, mm, o));
        if (lane == 0) wmax[wid] = mm;
    }
    __syncthreads();
    float m  = fmaxf(fmaxf(fmaxf(wmax[0], wmax[1]), fmaxf(wmax[2], wmax[3])), wmax[4]);
    float sc = __fdividef(1.0f, m);
    float L  = __logf(m);

    // ---- one scan step: half a 66-dot per thread + pair-shfl combine ----
    auto STEP = [&](int t, const float* uc, float* un, float scale, bool renorm) {
        float em = esh[t*TT + cc];
        const ulonglong2* u2 = (const ulonglong2*)(uc + h*36);  // h=0: +0B, h=1: +144B
        ull d0 = 0, d1 = 0;
        #pragma unroll
        for (int i = 0; i < 8; i++) {
            ulonglong2 v = u2[i];
            fma2(d0, v.x, e[2*i]);
            fma2(d1, v.y, e[2*i+1]);
        }
        ull lastp = *(const ull*)(uc + 68);     // (u64, u65)
        fma2(d0, lastp, e[16]);                 // h=1 contributes 0
        add2(d0, d0, d1);
        float2 f = upk2(d0);
        float s = f.x + f.y;
        s += __shfl_xor_sync(~0u, s, 1);        // combine the two halves
        r = act ? s * (scale * em) : 0.f;
        if (act && h == 0) un[loc] = r;
        if (renorm) {
            float mm = r;
            #pragma unroll
            for (int o = 16; o; o >>= 1) mm = fmaxf(mm, __shfl_xor_sync(~0u, mm, o));
            if (lane == 0) wmax[wid] = mm;
        }
        __syncthreads();
    };

    // ---- main scan: 15 groups of 8 + 7-step tail; renorm at group ends ----
    float* uc = ub;
    float* un = ub + USTR;
    int t = 1;
    for (int grp = 0; grp < 16; grp++) {
        const int nsteps = (grp == 15) ? 7 : 8;
        #pragma unroll 8
        for (int q = 0; q < nsteps; q++) {
            STEP(t, uc, un, (q == 0) ? sc : 1.0f, (q == nsteps-1) && (grp < 15));
            float* tmp = uc; uc = un; un = tmp;
            t++;
        }
        if (grp < 15) {
            m  = fmaxf(fmaxf(fmaxf(wmax[0], wmax[1]), fmaxf(wmax[2], wmax[3])), wmax[4]);
            sc = __fdividef(1.0f, m);
            L += __logf(m);
        }
    }

    // ---- epilogue: logZ = log(sum_c u_c * exp(end_c)) + L ----
    float contrib = r * eE;                    // h==1 and idle threads: eE = 0
    #pragma unroll
    for (int o = 16; o; o >>= 1) contrib += __shfl_xor_sync(~0u, contrib, o);
    if (lane == 0) swsum[wid] = contrib;
    __syncthreads();

    if (tid == 0) {
        float ws = (((swsum[0] + swsum[1]) + (swsum[2] + swsum[3])) + swsum[4]);
        float gt = (((sgold[0] + sgold[1]) + (sgold[2] + sgold[3])) + sgold[4]);
        __stcg(&g_partial[seq], __logf(ws) + L - gt);
        __threadfence();
        unsigned c0 = atomicAdd(&g_count, 1u);
        *sflag = (c0 == NSEQ - 1) ? 1 : 0;
    }
    __syncthreads();

    // ---- fused final reduction in the last block ----
    if (*sflag) {
        float v = 0.f;
        if (tid < 128) v = __ldcg(&g_partial[tid]) + __ldcg(&g_partial[tid + 128]);
        #pragma unroll
        for (int o = 16; o; o >>= 1) v += __shfl_xor_sync(~0u, v, o);
        if (lane == 0) wred[wid] = v;
        __syncthreads();
        if (tid == 0) {
            out[0] = (((wred[0] + wred[1]) + (wred[2] + wred[3])) + wred[4])
                     * (1.0f / (float)NSEQ);
            g_count = 0;                       // reset for next graph replay
        }
    }
}

extern "C" void kernel_launch(void* const* d_in, const int* in_sizes, int n_in,
                              void* d_out, int out_size) {
    const float* score      = (const float*)d_in[0];
    const float* trans      = (const float*)d_in[1];
    const float* startT     = (const float*)d_in[2];
    const float* endT       = (const float*)d_in[3];
    const int*   v_label    = (const int*)d_in[4];
    const int*   role_label = (const int*)d_in[5];
    float* out = (float*)d_out;

    cudaFuncSetAttribute(crf_kernel,
                         cudaFuncAttributeMaxDynamicSharedMemorySize, SMEM_BYTES);

    crf_kernel<<<NSEQ, NTHR, SMEM_BYTES>>>(
        score, trans, startT, endT, v_label, role_label, out);
}